// round 14
// baseline (speedup 1.0000x reference)
#include <cuda_runtime.h>
#include <cuda_bf16.h>
#include <cfloat>
#include <math.h>
#include <cstdint>

// ---------------------------------------------------------------------------
//   z2: (8,128,24,24)  y1: (8,192,96,96)
//   cat = concat(upsample4x(z2), y1) : (8,320,96,96)
//   sigma = relu(c5(relu(c5(relu(c5(cat,ws1)),ws2)),ws3))        -> (8,576,96,96)
//   means = c5(lrelu(c5(lrelu(c5(cat,wm1)),wm2)),wm3)            -> (8,576,96,96)
//   w     = softmax_K( c1x1( lrelu( maxHW( c5(lrelu(c5(cat,ww1)),ww2) ))))
// Output packing: [sigma | means | weights]
// Conv via mma.sync m16n8k16 bf16, hi/lo 3-term; branch-fused launches;
// fused prep (UPS_N fixed: 23,592,960 — R12/R13 had 10x-too-small constant);
// operand loads hoisted to kx-group top.
// ---------------------------------------------------------------------------
#define BATCH 8
#define CH_Z 128
#define CH_Y 192
#define CH_CAT 320
#define CH_N 128
#define CH_MK 576
#define HW 96
#define HW2 (HW*HW)

// -------------------- scratch (static device globals; no allocs) ------------
__device__ uint32_t g_cat[BATCH * 20 * HW2 * 16];   // 94.4 MB
__device__ uint32_t g_t1s[BATCH *  8 * HW2 * 16];
__device__ uint32_t g_t1m[BATCH *  8 * HW2 * 16];
__device__ uint32_t g_t1w[BATCH *  8 * HW2 * 16];
__device__ uint32_t g_t2s[BATCH *  8 * HW2 * 16];
__device__ uint32_t g_t2m[BATCH *  8 * HW2 * 16];
__device__ float    g_pool[BATCH * CH_MK];
__device__ uint32_t g_wT[9420800];

#define O_WS1 0u
#define O_WS2 1024000u
#define O_WS3 1433600u
#define O_WM1 3276800u
#define O_WM2 4300800u
#define O_WM3 4710400u
#define O_WW1 6553600u
#define O_WW2 7577600u

__device__ __forceinline__ uint32_t smem_to_u32(const void* smem_ptr) {
    uint32_t addr;
    asm("{ .reg .u64 tmp; cvta.to.shared.u64 tmp, %1; cvt.u32.u64 %0, tmp; }"
        : "=r"(addr) : "l"(smem_ptr));
    return addr;
}
__device__ __forceinline__ void ldsm4(uint32_t a[4], uint32_t addr) {
    asm volatile("ldmatrix.sync.aligned.m8n8.x4.shared.b16 {%0,%1,%2,%3}, [%4];"
        : "=r"(a[0]), "=r"(a[1]), "=r"(a[2]), "=r"(a[3]) : "r"(addr));
}
__device__ __forceinline__ void mma16816(float c[4], const uint32_t a[4],
                                         const uint32_t b0, const uint32_t b1) {
    asm volatile("mma.sync.aligned.m16n8k16.row.col.f32.bf16.bf16.f32 "
        "{%0,%1,%2,%3}, {%4,%5,%6,%7}, {%8,%9}, {%0,%1,%2,%3};"
        : "+f"(c[0]), "+f"(c[1]), "+f"(c[2]), "+f"(c[3])
        : "r"(a[0]), "r"(a[1]), "r"(a[2]), "r"(a[3]), "r"(b0), "r"(b1));
}
__device__ __forceinline__ void cp16(uint32_t dst, const void* src) {
    asm volatile("cp.async.cg.shared.global [%0], [%1], 16;\n"
        :: "r"(dst), "l"(src));
}
__device__ __forceinline__ void cp16_zfill(uint32_t dst, const void* src) {
    asm volatile("cp.async.cg.shared.global [%0], [%1], 16, 0;\n"
        :: "r"(dst), "l"(src));
}
#define CP_COMMIT asm volatile("cp.async.commit_group;\n" ::: "memory")
#define CP_WAIT0  asm volatile("cp.async.wait_group 0;\n" ::: "memory")

__device__ __forceinline__ void atomicMaxFloat(float* addr, float v) {
    if (v >= 0.0f) atomicMax((int*)addr, __float_as_int(v));
    else           atomicMin((unsigned int*)addr, __float_as_uint(v));
}
__device__ __forceinline__ void split2(float v, uint16_t& h, uint16_t& l) {
    __nv_bfloat16 bh = __float2bfloat16(v);
    __nv_bfloat16 bl = __float2bfloat16(v - __bfloat162float(bh));
    h = *reinterpret_cast<uint16_t*>(&bh);
    l = *reinterpret_cast<uint16_t*>(&bl);
}

// -------------------- fused prep: weights + upsample/concat + pool ----------
struct WPack { const float* w[8]; };
#define WPREP_N   4710400u
#define UPS_N     23592960u         // BATCH*CH_CAT*HW2 = 8*320*9216 (FIXED)
#define POOL_N    4608u

__global__ void prep_all_kernel(WPack wp, const float* __restrict__ z2,
                                const float* __restrict__ y1) {
    uint32_t gid = blockIdx.x * blockDim.x + threadIdx.x;
    if (gid < WPREP_N) {
        const int coutA[8] = {128,128,576,128,128,576,128,576};
        const int cinA [8] = {320,128,128,320,128,128,320,128};
        const uint32_t offA[8] = {O_WS1,O_WS2,O_WS3,O_WM1,O_WM2,O_WM3,O_WW1,O_WW2};
        const uint32_t cum[9] = {0u,512000u,716800u,1638400u,2150400u,2355200u,
                                 3276800u,3788800u,4710400u};
        uint32_t d = gid;
        int L = 0;
        #pragma unroll
        for (int i = 1; i < 8; i++) if (d >= cum[i]) L = i;
        uint32_t r = d - cum[L];
        const int cout = coutA[L], cin = cinA[L], nch = cin >> 4;
        int cp  = r & 7;
        int oc  = (r >> 3) % cout;
        uint32_t q = (r >> 3) / cout;
        int ch  = q % nch;
        int tap = q / nch;
        int c0  = ch * 16 + cp * 2;
        const float* w = wp.w[L];
        float v0 = w[((size_t)oc * cin + c0) * 25 + tap];
        float v1 = w[((size_t)oc * cin + c0 + 1) * 25 + tap];
        uint16_t h0, l0, h1, l1;
        split2(v0, h0, l0); split2(v1, h1, l1);
        uint32_t base = offA[L] + (((uint32_t)tap * nch + ch) * cout + oc) * 16;
        g_wT[base + cp]     = (uint32_t)h0 | ((uint32_t)h1 << 16);
        g_wT[base + 8 + cp] = (uint32_t)l0 | ((uint32_t)l1 << 16);
        return;
    }
    gid -= WPREP_N;
    if (gid < UPS_N) {
        int idx = (int)gid;
        int x = idx % HW;
        int y = (idx / HW) % HW;
        int c = (idx / HW2) % CH_CAT;
        int n = idx / (CH_CAT * HW2);
        float v;
        if (c >= CH_Z) {
            v = y1[((n * CH_Y + (c - CH_Z)) * HW + y) * HW + x];
        } else {
            float fy = (float)((double)y * 23.0 / 95.0);
            float fx = (float)((double)x * 23.0 / 95.0);
            int y0 = (int)floorf(fy); int y1i = min(y0 + 1, 23);
            int x0 = (int)floorf(fx); int x1i = min(x0 + 1, 23);
            float wy = fy - (float)y0;
            float wx = fx - (float)x0;
            const float* src = z2 + ((n * CH_Z + c) * 24) * 24;
            float v00 = src[y0 * 24 + x0], v01 = src[y0 * 24 + x1i];
            float v10 = src[y1i * 24 + x0], v11 = src[y1i * 24 + x1i];
            float r0 = v00 * (1.f - wx) + v01 * wx;
            float r1 = v10 * (1.f - wx) + v11 * wx;
            v = r0 * (1.f - wy) + r1 * wy;
        }
        uint16_t h, l; split2(v, h, l);
        unsigned char* cb = (unsigned char*)g_cat;
        size_t byte = ((((size_t)n * 20 + (c >> 4)) * HW + y) * HW + x) * 64 + (c & 15) * 2;
        *(uint16_t*)(cb + byte)      = h;
        *(uint16_t*)(cb + byte + 32) = l;
        return;
    }
    gid -= UPS_N;
    if (gid < POOL_N) g_pool[gid] = -FLT_MAX;
}

// ===================== mma.sync conv5x5 (fused segments) =====================
#define HHR 12
#define HHC 36
#define NPX (HHR * HHC)        // 432
#define BBUF (NPX * 64)        // 27648
#define A_TAP (64 * 64)        // 4096
#define A_BUF (5 * A_TAP)      // 20480
#define SM_A 0
#define SM_B (2 * A_BUF)       // 40960
#define SMEM_BYTES (SM_B + 2 * BBUF)   // 96256

__device__ __forceinline__ uint32_t swz(int row, int part) {
    return (uint32_t)((part ^ ((row >> 1) & 3)) << 4);
}

struct Seg {
    const unsigned char* in;
    const unsigned char* w;
    const float* bias;
    void* out;
    float* maxout;
    int cout;
    int ntiles;
    int act;         // 0 none, 1 relu, 2 lrelu
    int packed_out;  // 1: packed hi/lo bf16 layout, 0: fp32 NCHW
};
struct Launch3 {
    Seg s[3];
    int nseg;
    int cin;
};

__global__ __launch_bounds__(256, 2)
void conv5x5_mma_kernel(Launch3 L) {
    extern __shared__ unsigned char sm[];
    const uint32_t smu = smem_to_u32(sm);
    const int tid = threadIdx.x, wid = tid >> 5, lane = tid & 31;
    const int n   = blockIdx.z;
    const int xb  = (blockIdx.x % 3) * 32;
    const int rb  = (blockIdx.x / 3) * 8;
    const int cin = L.cin;
    const int nch = cin >> 4;

    // segment lookup (block-uniform)
    int yt = blockIdx.y, si = 0;
    while (si < L.nseg - 1 && yt >= L.s[si].ntiles) { yt -= L.s[si].ntiles; si++; }
    const unsigned char* in   = L.s[si].in;
    const unsigned char* wfmt = L.s[si].w;
    const float* bias  = L.s[si].bias;
    void*  outp        = L.s[si].out;
    float* maxout      = L.s[si].maxout;
    const int cout     = L.s[si].cout;
    const int act      = L.s[si].act;
    const int packed_out = L.s[si].packed_out;
    const int ocb = yt * 64;

    float acc[4][4][4];
    #pragma unroll
    for (int m = 0; m < 4; m++)
        #pragma unroll
        for (int j = 0; j < 4; j++)
            #pragma unroll
            for (int q = 0; q < 4; q++) acc[m][j][q] = 0.0f;

    // ---- staging helpers ----
    auto stageB = [&](int ch, int buf) {
        const unsigned char* bb = in + ((size_t)(n * nch + ch) * HW2) * 64;
        const uint32_t dstb = smu + SM_B + buf * BBUF;
        for (int i = tid; i < NPX * 4; i += 256) {
            int px = i >> 2, part = i & 3;
            int hy = px / HHC, hx = px - hy * HHC;
            int gy = rb + hy - 2, gx = xb + hx - 2;
            uint32_t dst = dstb + px * 64 + swz(px, part);
            if ((unsigned)gy < (unsigned)HW && (unsigned)gx < (unsigned)HW)
                cp16(dst, bb + ((size_t)gy * HW + gx) * 64 + part * 16);
            else
                cp16_zfill(dst, bb);
        }
    };
    auto stageA = [&](int ch, int ky, int buf) {
        const unsigned char* ab = wfmt + (((size_t)(ky * 5) * nch + ch) * cout + ocb) * 64;
        const uint32_t abuf = smu + SM_A + buf * A_BUF;
        for (int i = tid; i < 1280; i += 256) {
            int part = i & 3, oc = (i >> 2) & 63, t = i >> 8;
            uint32_t dst = abuf + t * A_TAP + oc * 64 + swz(oc, part);
            cp16(dst, ab + ((size_t)t * nch * cout + oc) * 64 + part * 16);
        }
    };

    // ---- preload chunk 0 ----
    int ap = 0, bc = 0;
    stageB(0, 0);
    stageA(0, 0, 0);
    CP_COMMIT; CP_WAIT0; __syncthreads();

    for (int ch = 0; ch < nch; ch++) {
        for (int ky = 0; ky < 5; ky++) {
            // prefetch
            if (ky < 4) {
                stageA(ch, ky + 1, ap ^ 1);
                CP_COMMIT;
            } else if (ch + 1 < nch) {
                stageB(ch + 1, bc ^ 1);
                stageA(ch + 1, 0, ap ^ 1);
                CP_COMMIT;
            }

            // compute ky with A[ap], B[bc]
            #pragma unroll
            for (int kx = 0; kx < 5; kx++) {
                const int arow = lane & 15;
                const int ah   = lane >> 4;          // 0 or 1 (16B column)
                const uint32_t arowb = smu + SM_A + ap * A_BUF + kx * A_TAP + arow * 64;
                const int pbase = (wid + ky) * HHC + kx + (lane >> 2);
                const uint32_t bbufb = SM_B + bc * BBUF;
                const int lc = (lane & 3) * 4;

                uint32_t a_hi[4][4], a_lo[4][4];
                uint32_t b_f[4][2], b_g[4][2];

                // ---- all operand loads up front (independent chains) ----
                #pragma unroll
                for (int m = 0; m < 4; m++)
                    ldsm4(a_hi[m], arowb + m * 16 * 64 + swz(arow, ah));
                #pragma unroll
                for (int m = 0; m < 4; m++)
                    ldsm4(a_lo[m], arowb + m * 16 * 64 + swz(arow, 2 + ah));
                #pragma unroll
                for (int j = 0; j < 4; j++) {
                    int px = pbase + j * 8;
                    const unsigned char* bp = sm + bbufb + px * 64;
                    b_f[j][0] = *(const uint32_t*)(bp + swz(px, 0) + lc);
                    b_f[j][1] = *(const uint32_t*)(bp + swz(px, 1) + lc);
                    b_g[j][0] = *(const uint32_t*)(bp + swz(px, 2) + lc);
                    b_g[j][1] = *(const uint32_t*)(bp + swz(px, 3) + lc);
                }

                // ---- 3 MMA term groups ----
                #pragma unroll
                for (int m = 0; m < 4; m++)
                    #pragma unroll
                    for (int j = 0; j < 4; j++)
                        mma16816(acc[m][j], a_hi[m], b_f[j][0], b_f[j][1]);
                #pragma unroll
                for (int m = 0; m < 4; m++)
                    #pragma unroll
                    for (int j = 0; j < 4; j++)
                        mma16816(acc[m][j], a_lo[m], b_f[j][0], b_f[j][1]);
                #pragma unroll
                for (int m = 0; m < 4; m++)
                    #pragma unroll
                    for (int j = 0; j < 4; j++)
                        mma16816(acc[m][j], a_hi[m], b_g[j][0], b_g[j][1]);
            }

            // drain prefetch + make visible (skip after the very last tile)
            if (!(ky == 4 && ch + 1 == nch)) {
                CP_WAIT0; __syncthreads();
            }
            ap ^= 1;
        }
        bc ^= 1;
    }

    // ===================== epilogue =====================
    const int gy = rb + wid;
    if (maxout != nullptr) {
        #pragma unroll
        for (int m = 0; m < 4; m++) {
            float m0 = -FLT_MAX, m1 = -FLT_MAX;
            #pragma unroll
            for (int j = 0; j < 4; j++) {
                m0 = fmaxf(m0, fmaxf(acc[m][j][0], acc[m][j][1]));
                m1 = fmaxf(m1, fmaxf(acc[m][j][2], acc[m][j][3]));
            }
            #pragma unroll
            for (int d = 1; d < 4; d <<= 1) {
                m0 = fmaxf(m0, __shfl_xor_sync(0xffffffffu, m0, d));
                m1 = fmaxf(m1, __shfl_xor_sync(0xffffffffu, m1, d));
            }
            if ((lane & 3) == 0) {
                const int oc0 = ocb + m * 16 + (lane >> 2);
                atomicMaxFloat(&maxout[n * cout + oc0], m0);
                atomicMaxFloat(&maxout[n * cout + oc0 + 8], m1);
            }
        }
    } else if (packed_out) {
        unsigned char* ob = (unsigned char*)outp;
        const int nchO = cout >> 4;
        #pragma unroll
        for (int m = 0; m < 4; m++) {
            const int ocA = ocb + m * 16 + (lane >> 2);
            const float bA = bias[ocA], bB = bias[ocA + 8];
            const int sA = (ocA & 15) * 2, sB = sA + 16;
            unsigned char* rowb = ob + ((((size_t)n * nchO + (ocA >> 4)) * HW + gy) * HW) * 64;
            #pragma unroll
            for (int j = 0; j < 4; j++) {
                const int x = xb + j * 8 + (lane & 3) * 2;
                float v0 = acc[m][j][0] + bA, v1 = acc[m][j][1] + bA;
                float v2 = acc[m][j][2] + bB, v3 = acc[m][j][3] + bB;
                if (act == 1) {
                    v0 = fmaxf(v0, 0.f); v1 = fmaxf(v1, 0.f);
                    v2 = fmaxf(v2, 0.f); v3 = fmaxf(v3, 0.f);
                } else if (act == 2) {
                    v0 = v0 >= 0.f ? v0 : 0.01f * v0;
                    v1 = v1 >= 0.f ? v1 : 0.01f * v1;
                    v2 = v2 >= 0.f ? v2 : 0.01f * v2;
                    v3 = v3 >= 0.f ? v3 : 0.01f * v3;
                }
                unsigned char* p0 = rowb + (size_t)x * 64;
                uint16_t h, l;
                split2(v0, h, l); *(uint16_t*)(p0 + sA) = h;       *(uint16_t*)(p0 + 32 + sA) = l;
                split2(v1, h, l); *(uint16_t*)(p0 + 64 + sA) = h;  *(uint16_t*)(p0 + 96 + sA) = l;
                split2(v2, h, l); *(uint16_t*)(p0 + sB) = h;       *(uint16_t*)(p0 + 32 + sB) = l;
                split2(v3, h, l); *(uint16_t*)(p0 + 64 + sB) = h;  *(uint16_t*)(p0 + 96 + sB) = l;
            }
        }
    } else {
        float* out = (float*)outp;
        #pragma unroll
        for (int m = 0; m < 4; m++) {
            const int oc0 = ocb + m * 16 + (lane >> 2);
            const float b0 = bias[oc0], b1 = bias[oc0 + 8];
            float* r0 = out + (((size_t)n * cout + oc0) * HW + gy) * HW;
            float* r1 = out + (((size_t)n * cout + oc0 + 8) * HW + gy) * HW;
            #pragma unroll
            for (int j = 0; j < 4; j++) {
                const int x = xb + j * 8 + (lane & 3) * 2;
                float v0 = acc[m][j][0] + b0, v1 = acc[m][j][1] + b0;
                float v2 = acc[m][j][2] + b1, v3 = acc[m][j][3] + b1;
                if (act == 1) {
                    v0 = fmaxf(v0, 0.f); v1 = fmaxf(v1, 0.f);
                    v2 = fmaxf(v2, 0.f); v3 = fmaxf(v3, 0.f);
                } else if (act == 2) {
                    v0 = v0 >= 0.f ? v0 : 0.01f * v0;
                    v1 = v1 >= 0.f ? v1 : 0.01f * v1;
                    v2 = v2 >= 0.f ? v2 : 0.01f * v2;
                    v3 = v3 >= 0.f ? v3 : 0.01f * v3;
                }
                *reinterpret_cast<float2*>(r0 + x) = make_float2(v0, v1);
                *reinterpret_cast<float2*>(r1 + x) = make_float2(v2, v3);
            }
        }
    }
}

// -------------------- final: bias+lrelu pooled -> 1x1 conv -> softmax --------
__global__ void final_kernel(const float* __restrict__ bw2,
                             const float* __restrict__ ww3,
                             const float* __restrict__ bw3,
                             float* __restrict__ out_w) {
    __shared__ float sp_[CH_MK];
    __shared__ float sv_[CH_MK];
    const int c = threadIdx.x;
    const int n = blockIdx.x;
    float pv = g_pool[n * CH_MK + c] + bw2[c];
    sp_[c] = pv >= 0.f ? pv : 0.01f * pv;
    __syncthreads();
    float sacc = bw3[c];
    const float* wr = ww3 + c * CH_MK;
    for (int i = 0; i < CH_MK; i++) sacc += wr[i] * sp_[i];
    sv_[c] = sacc;
    __syncthreads();
    const int m = c % 192;
    float e0 = sv_[m], e1 = sv_[m + 192], e2 = sv_[m + 384];
    float mx = fmaxf(e0, fmaxf(e1, e2));
    float den = expf(e0 - mx) + expf(e1 - mx) + expf(e2 - mx);
    out_w[n * CH_MK + c] = expf(sv_[c] - mx) / den;
}

// -------------------- launch ------------------------------------------------
extern "C" void kernel_launch(void* const* d_in, const int* in_sizes, int n_in,
                              void* d_out, int out_size) {
    const float* z2  = (const float*)d_in[0];
    const float* y1  = (const float*)d_in[1];
    const float* ws1 = (const float*)d_in[2];  const float* bs1 = (const float*)d_in[3];
    const float* ws2 = (const float*)d_in[4];  const float* bs2 = (const float*)d_in[5];
    const float* ws3 = (const float*)d_in[6];  const float* bs3 = (const float*)d_in[7];
    const float* wm1 = (const float*)d_in[8];  const float* bm1 = (const float*)d_in[9];
    const float* wm2 = (const float*)d_in[10]; const float* bm2 = (const float*)d_in[11];
    const float* wm3 = (const float*)d_in[12]; const float* bm3 = (const float*)d_in[13];
    const float* ww1 = (const float*)d_in[14]; const float* bw1 = (const float*)d_in[15];
    const float* ww2 = (const float*)d_in[16]; const float* bw2 = (const float*)d_in[17];
    const float* ww3 = (const float*)d_in[18]; const float* bw3 = (const float*)d_in[19];

    float* out = (float*)d_out;
    const size_t MEAN_OFF = (size_t)BATCH * CH_MK * HW2;
    const size_t W_OFF    = 2 * MEAN_OFF;

    void* p;
    cudaGetSymbolAddress(&p, g_cat); unsigned char* cat = (unsigned char*)p;
    cudaGetSymbolAddress(&p, g_t1s); unsigned char* t1s = (unsigned char*)p;
    cudaGetSymbolAddress(&p, g_t1m); unsigned char* t1m = (unsigned char*)p;
    cudaGetSymbolAddress(&p, g_t1w); unsigned char* t1w = (unsigned char*)p;
    cudaGetSymbolAddress(&p, g_t2s); unsigned char* t2s = (unsigned char*)p;
    cudaGetSymbolAddress(&p, g_t2m); unsigned char* t2m = (unsigned char*)p;
    cudaGetSymbolAddress(&p, g_pool); float* pool = (float*)p;
    cudaGetSymbolAddress(&p, g_wT);  unsigned char* wb = (unsigned char*)p;

    cudaFuncSetAttribute(conv5x5_mma_kernel,
                         cudaFuncAttributeMaxDynamicSharedMemorySize, SMEM_BYTES);

    // launch 1: fused prep (weights + upsample/concat + pool init)
    {
        WPack wp;
        wp.w[0] = ws1; wp.w[1] = ws2; wp.w[2] = ws3;
        wp.w[3] = wm1; wp.w[4] = wm2; wp.w[5] = wm3;
        wp.w[6] = ww1; wp.w[7] = ww2;
        uint32_t total = WPREP_N + UPS_N + POOL_N;   // 28,307,968
        prep_all_kernel<<<(total + 255) / 256, 256>>>(wp, z2, y1);
    }

    dim3 blk(256);

    // launch 2: layer 1 (cat -> t1s/t1m/t1w), cin=320, 6 tiles
    {
        Launch3 L{};
        L.nseg = 3; L.cin = CH_CAT;
        L.s[0] = { cat, wb + (size_t)O_WS1 * 4, bs1, t1s, nullptr, CH_N, 2, 1, 1 };
        L.s[1] = { cat, wb + (size_t)O_WM1 * 4, bm1, t1m, nullptr, CH_N, 2, 2, 1 };
        L.s[2] = { cat, wb + (size_t)O_WW1 * 4, bw1, t1w, nullptr, CH_N, 2, 2, 1 };
        conv5x5_mma_kernel<<<dim3(36, 6, BATCH), blk, SMEM_BYTES>>>(L);
    }
    // launch 3: layer 2 (t1s->t2s, t1m->t2m, t1w->pool), cin=128, 13 tiles
    {
        Launch3 L{};
        L.nseg = 3; L.cin = CH_N;
        L.s[0] = { t1s, wb + (size_t)O_WS2 * 4, bs2, t2s, nullptr, CH_N, 2, 1, 1 };
        L.s[1] = { t1m, wb + (size_t)O_WM2 * 4, bm2, t2m, nullptr, CH_N, 2, 2, 1 };
        L.s[2] = { t1w, wb + (size_t)O_WW2 * 4, nullptr, nullptr, pool, CH_MK, 9, 0, 0 };
        conv5x5_mma_kernel<<<dim3(36, 13, BATCH), blk, SMEM_BYTES>>>(L);
    }
    // launch 4: layer 3 (t2s->sigma, t2m->means), cin=128, 18 tiles
    {
        Launch3 L{};
        L.nseg = 2; L.cin = CH_N;
        L.s[0] = { t2s, wb + (size_t)O_WS3 * 4, bs3, out, nullptr, CH_MK, 9, 1, 0 };
        L.s[1] = { t2m, wb + (size_t)O_WM3 * 4, bm3, out + MEAN_OFF, nullptr, CH_MK, 9, 0, 0 };
        conv5x5_mma_kernel<<<dim3(36, 18, BATCH), blk, SMEM_BYTES>>>(L);
    }
    // launch 5: final softmax head
    final_kernel<<<BATCH, CH_MK>>>(bw2, ww3, bw3, out + W_OFF);
}

// round 15
// speedup vs baseline: 1.0355x; 1.0355x over previous
#include <cuda_runtime.h>
#include <cuda_bf16.h>
#include <cfloat>
#include <math.h>
#include <cstdint>

// ---------------------------------------------------------------------------
//   z2: (8,128,24,24)  y1: (8,192,96,96)
//   cat = concat(upsample4x(z2), y1) : (8,320,96,96)
//   sigma = relu(c5(relu(c5(relu(c5(cat,ws1)),ws2)),ws3))        -> (8,576,96,96)
//   means = c5(lrelu(c5(lrelu(c5(cat,wm1)),wm2)),wm3)            -> (8,576,96,96)
//   w     = softmax_K( c1x1( lrelu( maxHW( c5(lrelu(c5(cat,ww1)),ww2) ))))
// Output packing: [sigma | means | weights]
// Conv via mma.sync m16n8k16 bf16, hi/lo 3-term; branch-fused conv launches.
// Base = R10 (9655us passing). Single change: B fragments via ldmatrix.x2
// instead of 16x LDS.32 per kx group (same layout, same liveness).
// ---------------------------------------------------------------------------
#define BATCH 8
#define CH_Z 128
#define CH_Y 192
#define CH_CAT 320
#define CH_N 128
#define CH_MK 576
#define HW 96
#define HW2 (HW*HW)

// -------------------- scratch (static device globals; no allocs) ------------
__device__ uint32_t g_cat[BATCH * 20 * HW2 * 16];   // 94.4 MB
__device__ uint32_t g_t1s[BATCH *  8 * HW2 * 16];
__device__ uint32_t g_t1m[BATCH *  8 * HW2 * 16];
__device__ uint32_t g_t1w[BATCH *  8 * HW2 * 16];
__device__ uint32_t g_t2s[BATCH *  8 * HW2 * 16];
__device__ uint32_t g_t2m[BATCH *  8 * HW2 * 16];
__device__ float    g_pool[BATCH * CH_MK];
__device__ uint32_t g_wT[9420800];

#define O_WS1 0u
#define O_WS2 1024000u
#define O_WS3 1433600u
#define O_WM1 3276800u
#define O_WM2 4300800u
#define O_WM3 4710400u
#define O_WW1 6553600u
#define O_WW2 7577600u

__device__ __forceinline__ uint32_t smem_to_u32(const void* smem_ptr) {
    uint32_t addr;
    asm("{ .reg .u64 tmp; cvta.to.shared.u64 tmp, %1; cvt.u32.u64 %0, tmp; }"
        : "=r"(addr) : "l"(smem_ptr));
    return addr;
}
__device__ __forceinline__ void ldsm4(uint32_t a[4], uint32_t addr) {
    asm volatile("ldmatrix.sync.aligned.m8n8.x4.shared.b16 {%0,%1,%2,%3}, [%4];"
        : "=r"(a[0]), "=r"(a[1]), "=r"(a[2]), "=r"(a[3]) : "r"(addr));
}
__device__ __forceinline__ void ldsm2(uint32_t a[2], uint32_t addr) {
    asm volatile("ldmatrix.sync.aligned.m8n8.x2.shared.b16 {%0,%1}, [%2];"
        : "=r"(a[0]), "=r"(a[1]) : "r"(addr));
}
__device__ __forceinline__ void mma16816(float c[4], const uint32_t a[4],
                                         const uint32_t b0, const uint32_t b1) {
    asm volatile("mma.sync.aligned.m16n8k16.row.col.f32.bf16.bf16.f32 "
        "{%0,%1,%2,%3}, {%4,%5,%6,%7}, {%8,%9}, {%0,%1,%2,%3};"
        : "+f"(c[0]), "+f"(c[1]), "+f"(c[2]), "+f"(c[3])
        : "r"(a[0]), "r"(a[1]), "r"(a[2]), "r"(a[3]), "r"(b0), "r"(b1));
}
__device__ __forceinline__ void cp16(uint32_t dst, const void* src) {
    asm volatile("cp.async.cg.shared.global [%0], [%1], 16;\n"
        :: "r"(dst), "l"(src));
}
__device__ __forceinline__ void cp16_zfill(uint32_t dst, const void* src) {
    asm volatile("cp.async.cg.shared.global [%0], [%1], 16, 0;\n"
        :: "r"(dst), "l"(src));
}
#define CP_COMMIT asm volatile("cp.async.commit_group;\n" ::: "memory")
#define CP_WAIT0  asm volatile("cp.async.wait_group 0;\n" ::: "memory")

__device__ __forceinline__ void atomicMaxFloat(float* addr, float v) {
    if (v >= 0.0f) atomicMax((int*)addr, __float_as_int(v));
    else           atomicMin((unsigned int*)addr, __float_as_uint(v));
}
__device__ __forceinline__ void split2(float v, uint16_t& h, uint16_t& l) {
    __nv_bfloat16 bh = __float2bfloat16(v);
    __nv_bfloat16 bl = __float2bfloat16(v - __bfloat162float(bh));
    h = *reinterpret_cast<uint16_t*>(&bh);
    l = *reinterpret_cast<uint16_t*>(&bl);
}

// -------------------- weight prep (R10: separate launches) ------------------
struct WPack { const float* w[8]; };
__global__ void wprep_all_kernel(WPack wp) {
    const int coutA[8] = {128,128,576,128,128,576,128,576};
    const int cinA [8] = {320,128,128,320,128,128,320,128};
    const uint32_t offA[8] = {O_WS1,O_WS2,O_WS3,O_WM1,O_WM2,O_WM3,O_WW1,O_WW2};
    const uint32_t cum[9] = {0u,512000u,716800u,1638400u,2150400u,2355200u,
                             3276800u,3788800u,4710400u};
    uint32_t d = blockIdx.x * blockDim.x + threadIdx.x;
    if (d >= 4710400u) return;
    int L = 0;
    #pragma unroll
    for (int i = 1; i < 8; i++) if (d >= cum[i]) L = i;
    uint32_t r = d - cum[L];
    const int cout = coutA[L], cin = cinA[L], nch = cin >> 4;
    int cp  = r & 7;
    int oc  = (r >> 3) % cout;
    uint32_t q = (r >> 3) / cout;
    int ch  = q % nch;
    int tap = q / nch;
    int c0  = ch * 16 + cp * 2;
    const float* w = wp.w[L];
    float v0 = w[((size_t)oc * cin + c0) * 25 + tap];
    float v1 = w[((size_t)oc * cin + c0 + 1) * 25 + tap];
    uint16_t h0, l0, h1, l1;
    split2(v0, h0, l0); split2(v1, h1, l1);
    uint32_t base = offA[L] + (((uint32_t)tap * nch + ch) * cout + oc) * 16;
    g_wT[base + cp]     = (uint32_t)h0 | ((uint32_t)h1 << 16);
    g_wT[base + 8 + cp] = (uint32_t)l0 | ((uint32_t)l1 << 16);
}

// -------------------- upsample + concat (packed-split output) ----------------
__global__ void upsample_concat_kernel(const float* __restrict__ z2,
                                       const float* __restrict__ y1) {
    int idx = blockIdx.x * blockDim.x + threadIdx.x;
    const int total = BATCH * CH_CAT * HW2;
    if (idx >= total) return;
    int x = idx % HW;
    int y = (idx / HW) % HW;
    int c = (idx / HW2) % CH_CAT;
    int n = idx / (CH_CAT * HW2);
    float v;
    if (c >= CH_Z) {
        v = y1[((n * CH_Y + (c - CH_Z)) * HW + y) * HW + x];
    } else {
        float fy = (float)((double)y * 23.0 / 95.0);
        float fx = (float)((double)x * 23.0 / 95.0);
        int y0 = (int)floorf(fy); int y1i = min(y0 + 1, 23);
        int x0 = (int)floorf(fx); int x1i = min(x0 + 1, 23);
        float wy = fy - (float)y0;
        float wx = fx - (float)x0;
        const float* src = z2 + ((n * CH_Z + c) * 24) * 24;
        float v00 = src[y0 * 24 + x0], v01 = src[y0 * 24 + x1i];
        float v10 = src[y1i * 24 + x0], v11 = src[y1i * 24 + x1i];
        float r0 = v00 * (1.f - wx) + v01 * wx;
        float r1 = v10 * (1.f - wx) + v11 * wx;
        v = r0 * (1.f - wy) + r1 * wy;
    }
    uint16_t h, l; split2(v, h, l);
    unsigned char* cb = (unsigned char*)g_cat;
    size_t byte = ((((size_t)n * 20 + (c >> 4)) * HW + y) * HW + x) * 64 + (c & 15) * 2;
    *(uint16_t*)(cb + byte)      = h;
    *(uint16_t*)(cb + byte + 32) = l;
}

__global__ void init_pool_kernel() {
    int i = blockIdx.x * blockDim.x + threadIdx.x;
    if (i < BATCH * CH_MK) g_pool[i] = -FLT_MAX;
}

// ===================== mma.sync conv5x5 (fused segments) =====================
#define HHR 12
#define HHC 36
#define NPX (HHR * HHC)        // 432
#define BBUF (NPX * 64)        // 27648
#define A_TAP (64 * 64)        // 4096
#define A_BUF (5 * A_TAP)      // 20480
#define SM_A 0
#define SM_B (2 * A_BUF)       // 40960
#define SMEM_BYTES (SM_B + 2 * BBUF)   // 96256

__device__ __forceinline__ uint32_t swz(int row, int part) {
    return (uint32_t)((part ^ ((row >> 1) & 3)) << 4);
}

struct Seg {
    const unsigned char* in;
    const unsigned char* w;
    const float* bias;
    void* out;
    float* maxout;
    int cout;
    int ntiles;
    int act;         // 0 none, 1 relu, 2 lrelu
    int packed_out;  // 1: packed hi/lo bf16 layout, 0: fp32 NCHW
};
struct Launch3 {
    Seg s[3];
    int nseg;
    int cin;
};

__global__ __launch_bounds__(256, 2)
void conv5x5_mma_kernel(Launch3 L) {
    extern __shared__ unsigned char sm[];
    const uint32_t smu = smem_to_u32(sm);
    const int tid = threadIdx.x, wid = tid >> 5, lane = tid & 31;
    const int n   = blockIdx.z;
    const int xb  = (blockIdx.x % 3) * 32;
    const int rb  = (blockIdx.x / 3) * 8;
    const int cin = L.cin;
    const int nch = cin >> 4;

    // segment lookup (block-uniform)
    int yt = blockIdx.y, si = 0;
    while (si < L.nseg - 1 && yt >= L.s[si].ntiles) { yt -= L.s[si].ntiles; si++; }
    const unsigned char* in   = L.s[si].in;
    const unsigned char* wfmt = L.s[si].w;
    const float* bias  = L.s[si].bias;
    void*  outp        = L.s[si].out;
    float* maxout      = L.s[si].maxout;
    const int cout     = L.s[si].cout;
    const int act      = L.s[si].act;
    const int packed_out = L.s[si].packed_out;
    const int ocb = yt * 64;

    float acc[4][4][4];
    #pragma unroll
    for (int m = 0; m < 4; m++)
        #pragma unroll
        for (int j = 0; j < 4; j++)
            #pragma unroll
            for (int q = 0; q < 4; q++) acc[m][j][q] = 0.0f;

    // ---- staging helpers ----
    auto stageB = [&](int ch, int buf) {
        const unsigned char* bb = in + ((size_t)(n * nch + ch) * HW2) * 64;
        const uint32_t dstb = smu + SM_B + buf * BBUF;
        for (int i = tid; i < NPX * 4; i += 256) {
            int px = i >> 2, part = i & 3;
            int hy = px / HHC, hx = px - hy * HHC;
            int gy = rb + hy - 2, gx = xb + hx - 2;
            uint32_t dst = dstb + px * 64 + swz(px, part);
            if ((unsigned)gy < (unsigned)HW && (unsigned)gx < (unsigned)HW)
                cp16(dst, bb + ((size_t)gy * HW + gx) * 64 + part * 16);
            else
                cp16_zfill(dst, bb);
        }
    };
    auto stageA = [&](int ch, int ky, int buf) {
        const unsigned char* ab = wfmt + (((size_t)(ky * 5) * nch + ch) * cout + ocb) * 64;
        const uint32_t abuf = smu + SM_A + buf * A_BUF;
        for (int i = tid; i < 1280; i += 256) {
            int part = i & 3, oc = (i >> 2) & 63, t = i >> 8;
            uint32_t dst = abuf + t * A_TAP + oc * 64 + swz(oc, part);
            cp16(dst, ab + ((size_t)t * nch * cout + oc) * 64 + part * 16);
        }
    };

    // ---- preload chunk 0 ----
    int ap = 0, bc = 0;
    stageB(0, 0);
    stageA(0, 0, 0);
    CP_COMMIT; CP_WAIT0; __syncthreads();

    for (int ch = 0; ch < nch; ch++) {
        for (int ky = 0; ky < 5; ky++) {
            // prefetch
            if (ky < 4) {
                stageA(ch, ky + 1, ap ^ 1);
                CP_COMMIT;
            } else if (ch + 1 < nch) {
                stageB(ch + 1, bc ^ 1);
                stageA(ch + 1, 0, ap ^ 1);
                CP_COMMIT;
            }

            // compute ky with A[ap], B[bc]  (R10 interleaved structure,
            // B fragments via ldmatrix.x2: lanes 0-7 -> part p0 tile rows,
            // lanes 8-15 -> part p0+1 tile rows; g-phase addr = f-phase ^ 0x20)
            #pragma unroll
            for (int kx = 0; kx < 5; kx++) {
                const int arow = lane & 15;
                const int ah   = lane >> 4;          // 0 or 1 (16B column)
                const uint32_t arowb = smu + SM_A + ap * A_BUF + kx * A_TAP + arow * 64;
                const int rowb0 = (wid + ky) * HHC + kx;
                const uint32_t bbase = smu + SM_B + bc * BBUF;
                const int prt = (lane >> 3) & 1;     // tile select within x2

                uint32_t a_hi[4][4], a_lo[4][4];
                uint32_t b_f[4][2];
                uint32_t badr[4];

                #pragma unroll
                for (int m = 0; m < 4; m++)
                    ldsm4(a_hi[m], arowb + m * 16 * 64 + swz(arow, ah));
                #pragma unroll
                for (int j = 0; j < 4; j++) {
                    int px = rowb0 + j * 8 + (lane & 7);
                    badr[j] = bbase + px * 64 + swz(px, prt);
                    ldsm2(b_f[j], badr[j]);
                }
                #pragma unroll
                for (int m = 0; m < 4; m++)
                    #pragma unroll
                    for (int j = 0; j < 4; j++)
                        mma16816(acc[m][j], a_hi[m], b_f[j][0], b_f[j][1]);

                #pragma unroll
                for (int m = 0; m < 4; m++)
                    ldsm4(a_lo[m], arowb + m * 16 * 64 + swz(arow, 2 + ah));
                #pragma unroll
                for (int m = 0; m < 4; m++)
                    #pragma unroll
                    for (int j = 0; j < 4; j++)
                        mma16816(acc[m][j], a_lo[m], b_f[j][0], b_f[j][1]);

                #pragma unroll
                for (int j = 0; j < 4; j++)
                    ldsm2(b_f[j], badr[j] ^ 0x20u);   // parts 2,3 (lo half)
                #pragma unroll
                for (int m = 0; m < 4; m++)
                    #pragma unroll
                    for (int j = 0; j < 4; j++)
                        mma16816(acc[m][j], a_hi[m], b_f[j][0], b_f[j][1]);
            }

            // drain prefetch + make visible (skip after the very last tile)
            if (!(ky == 4 && ch + 1 == nch)) {
                CP_WAIT0; __syncthreads();
            }
            ap ^= 1;
        }
        bc ^= 1;
    }

    // ===================== epilogue =====================
    const int gy = rb + wid;
    if (maxout != nullptr) {
        #pragma unroll
        for (int m = 0; m < 4; m++) {
            float m0 = -FLT_MAX, m1 = -FLT_MAX;
            #pragma unroll
            for (int j = 0; j < 4; j++) {
                m0 = fmaxf(m0, fmaxf(acc[m][j][0], acc[m][j][1]));
                m1 = fmaxf(m1, fmaxf(acc[m][j][2], acc[m][j][3]));
            }
            #pragma unroll
            for (int d = 1; d < 4; d <<= 1) {
                m0 = fmaxf(m0, __shfl_xor_sync(0xffffffffu, m0, d));
                m1 = fmaxf(m1, __shfl_xor_sync(0xffffffffu, m1, d));
            }
            if ((lane & 3) == 0) {
                const int oc0 = ocb + m * 16 + (lane >> 2);
                atomicMaxFloat(&maxout[n * cout + oc0], m0);
                atomicMaxFloat(&maxout[n * cout + oc0 + 8], m1);
            }
        }
    } else if (packed_out) {
        unsigned char* ob = (unsigned char*)outp;
        const int nchO = cout >> 4;
        #pragma unroll
        for (int m = 0; m < 4; m++) {
            const int ocA = ocb + m * 16 + (lane >> 2);
            const float bA = bias[ocA], bB = bias[ocA + 8];
            const int sA = (ocA & 15) * 2, sB = sA + 16;
            unsigned char* rowb = ob + ((((size_t)n * nchO + (ocA >> 4)) * HW + gy) * HW) * 64;
            #pragma unroll
            for (int j = 0; j < 4; j++) {
                const int x = xb + j * 8 + (lane & 3) * 2;
                float v0 = acc[m][j][0] + bA, v1 = acc[m][j][1] + bA;
                float v2 = acc[m][j][2] + bB, v3 = acc[m][j][3] + bB;
                if (act == 1) {
                    v0 = fmaxf(v0, 0.f); v1 = fmaxf(v1, 0.f);
                    v2 = fmaxf(v2, 0.f); v3 = fmaxf(v3, 0.f);
                } else if (act == 2) {
                    v0 = v0 >= 0.f ? v0 : 0.01f * v0;
                    v1 = v1 >= 0.f ? v1 : 0.01f * v1;
                    v2 = v2 >= 0.f ? v2 : 0.01f * v2;
                    v3 = v3 >= 0.f ? v3 : 0.01f * v3;
                }
                unsigned char* p0 = rowb + (size_t)x * 64;
                uint16_t h, l;
                split2(v0, h, l); *(uint16_t*)(p0 + sA) = h;       *(uint16_t*)(p0 + 32 + sA) = l;
                split2(v1, h, l); *(uint16_t*)(p0 + 64 + sA) = h;  *(uint16_t*)(p0 + 96 + sA) = l;
                split2(v2, h, l); *(uint16_t*)(p0 + sB) = h;       *(uint16_t*)(p0 + 32 + sB) = l;
                split2(v3, h, l); *(uint16_t*)(p0 + 64 + sB) = h;  *(uint16_t*)(p0 + 96 + sB) = l;
            }
        }
    } else {
        float* out = (float*)outp;
        #pragma unroll
        for (int m = 0; m < 4; m++) {
            const int oc0 = ocb + m * 16 + (lane >> 2);
            const float b0 = bias[oc0], b1 = bias[oc0 + 8];
            float* r0 = out + (((size_t)n * cout + oc0) * HW + gy) * HW;
            float* r1 = out + (((size_t)n * cout + oc0 + 8) * HW + gy) * HW;
            #pragma unroll
            for (int j = 0; j < 4; j++) {
                const int x = xb + j * 8 + (lane & 3) * 2;
                float v0 = acc[m][j][0] + b0, v1 = acc[m][j][1] + b0;
                float v2 = acc[m][j][2] + b1, v3 = acc[m][j][3] + b1;
                if (act == 1) {
                    v0 = fmaxf(v0, 0.f); v1 = fmaxf(v1, 0.f);
                    v2 = fmaxf(v2, 0.f); v3 = fmaxf(v3, 0.f);
                } else if (act == 2) {
                    v0 = v0 >= 0.f ? v0 : 0.01f * v0;
                    v1 = v1 >= 0.f ? v1 : 0.01f * v1;
                    v2 = v2 >= 0.f ? v2 : 0.01f * v2;
                    v3 = v3 >= 0.f ? v3 : 0.01f * v3;
                }
                *reinterpret_cast<float2*>(r0 + x) = make_float2(v0, v1);
                *reinterpret_cast<float2*>(r1 + x) = make_float2(v2, v3);
            }
        }
    }
}

// -------------------- final: bias+lrelu pooled -> 1x1 conv -> softmax --------
__global__ void final_kernel(const float* __restrict__ bw2,
                             const float* __restrict__ ww3,
                             const float* __restrict__ bw3,
                             float* __restrict__ out_w) {
    __shared__ float sp_[CH_MK];
    __shared__ float sv_[CH_MK];
    const int c = threadIdx.x;
    const int n = blockIdx.x;
    float pv = g_pool[n * CH_MK + c] + bw2[c];
    sp_[c] = pv >= 0.f ? pv : 0.01f * pv;
    __syncthreads();
    float sacc = bw3[c];
    const float* wr = ww3 + c * CH_MK;
    for (int i = 0; i < CH_MK; i++) sacc += wr[i] * sp_[i];
    sv_[c] = sacc;
    __syncthreads();
    const int m = c % 192;
    float e0 = sv_[m], e1 = sv_[m + 192], e2 = sv_[m + 384];
    float mx = fmaxf(e0, fmaxf(e1, e2));
    float den = expf(e0 - mx) + expf(e1 - mx) + expf(e2 - mx);
    out_w[n * CH_MK + c] = expf(sv_[c] - mx) / den;
}

// -------------------- launch ------------------------------------------------
extern "C" void kernel_launch(void* const* d_in, const int* in_sizes, int n_in,
                              void* d_out, int out_size) {
    const float* z2  = (const float*)d_in[0];
    const float* y1  = (const float*)d_in[1];
    const float* ws1 = (const float*)d_in[2];  const float* bs1 = (const float*)d_in[3];
    const float* ws2 = (const float*)d_in[4];  const float* bs2 = (const float*)d_in[5];
    const float* ws3 = (const float*)d_in[6];  const float* bs3 = (const float*)d_in[7];
    const float* wm1 = (const float*)d_in[8];  const float* bm1 = (const float*)d_in[9];
    const float* wm2 = (const float*)d_in[10]; const float* bm2 = (const float*)d_in[11];
    const float* wm3 = (const float*)d_in[12]; const float* bm3 = (const float*)d_in[13];
    const float* ww1 = (const float*)d_in[14]; const float* bw1 = (const float*)d_in[15];
    const float* ww2 = (const float*)d_in[16]; const float* bw2 = (const float*)d_in[17];
    const float* ww3 = (const float*)d_in[18]; const float* bw3 = (const float*)d_in[19];

    float* out = (float*)d_out;
    const size_t MEAN_OFF = (size_t)BATCH * CH_MK * HW2;
    const size_t W_OFF    = 2 * MEAN_OFF;

    void* p;
    cudaGetSymbolAddress(&p, g_cat); unsigned char* cat = (unsigned char*)p;
    cudaGetSymbolAddress(&p, g_t1s); unsigned char* t1s = (unsigned char*)p;
    cudaGetSymbolAddress(&p, g_t1m); unsigned char* t1m = (unsigned char*)p;
    cudaGetSymbolAddress(&p, g_t1w); unsigned char* t1w = (unsigned char*)p;
    cudaGetSymbolAddress(&p, g_t2s); unsigned char* t2s = (unsigned char*)p;
    cudaGetSymbolAddress(&p, g_t2m); unsigned char* t2m = (unsigned char*)p;
    cudaGetSymbolAddress(&p, g_pool); float* pool = (float*)p;
    cudaGetSymbolAddress(&p, g_wT);  unsigned char* wb = (unsigned char*)p;

    cudaFuncSetAttribute(conv5x5_mma_kernel,
                         cudaFuncAttributeMaxDynamicSharedMemorySize, SMEM_BYTES);

    // launch 1: weight prep
    {
        WPack wp;
        wp.w[0] = ws1; wp.w[1] = ws2; wp.w[2] = ws3;
        wp.w[3] = wm1; wp.w[4] = wm2; wp.w[5] = wm3;
        wp.w[6] = ww1; wp.w[7] = ww2;
        wprep_all_kernel<<<(4710400 + 255) / 256, 256>>>(wp);
    }
    // launch 2: upsample+concat (packed)
    {
        int total = BATCH * CH_CAT * HW2;
        upsample_concat_kernel<<<(total + 255) / 256, 256>>>(z2, y1);
    }
    // launch 3: pool init
    init_pool_kernel<<<(BATCH * CH_MK + 255) / 256, 256>>>();

    dim3 blk(256);

    // launch 4: layer 1 (cat -> t1s/t1m/t1w), cin=320, 6 tiles
    {
        Launch3 L{};
        L.nseg = 3; L.cin = CH_CAT;
        L.s[0] = { cat, wb + (size_t)O_WS1 * 4, bs1, t1s, nullptr, CH_N, 2, 1, 1 };
        L.s[1] = { cat, wb + (size_t)O_WM1 * 4, bm1, t1m, nullptr, CH_N, 2, 2, 1 };
        L.s[2] = { cat, wb + (size_t)O_WW1 * 4, bw1, t1w, nullptr, CH_N, 2, 2, 1 };
        conv5x5_mma_kernel<<<dim3(36, 6, BATCH), blk, SMEM_BYTES>>>(L);
    }
    // launch 5: layer 2 (t1s->t2s, t1m->t2m, t1w->pool), cin=128, 13 tiles
    {
        Launch3 L{};
        L.nseg = 3; L.cin = CH_N;
        L.s[0] = { t1s, wb + (size_t)O_WS2 * 4, bs2, t2s, nullptr, CH_N, 2, 1, 1 };
        L.s[1] = { t1m, wb + (size_t)O_WM2 * 4, bm2, t2m, nullptr, CH_N, 2, 2, 1 };
        L.s[2] = { t1w, wb + (size_t)O_WW2 * 4, nullptr, nullptr, pool, CH_MK, 9, 0, 0 };
        conv5x5_mma_kernel<<<dim3(36, 13, BATCH), blk, SMEM_BYTES>>>(L);
    }
    // launch 6: layer 3 (t2s->sigma, t2m->means), cin=128, 18 tiles
    {
        Launch3 L{};
        L.nseg = 2; L.cin = CH_N;
        L.s[0] = { t2s, wb + (size_t)O_WS3 * 4, bs3, out, nullptr, CH_MK, 9, 1, 0 };
        L.s[1] = { t2m, wb + (size_t)O_WM3 * 4, bm3, out + MEAN_OFF, nullptr, CH_MK, 9, 0, 0 };
        conv5x5_mma_kernel<<<dim3(36, 18, BATCH), blk, SMEM_BYTES>>>(L);
    }
    // launch 7: final softmax head
    final_kernel<<<BATCH, CH_MK>>>(bw2, ww3, bw3, out + W_OFF);
}